// round 12
// baseline (speedup 1.0000x reference)
#include <cuda_runtime.h>
#include <cstdint>
#include <cstddef>

#define BB  2
#define NN  512
#define DD  256
#define DHH 16

// ---------------- scratch (no allocations allowed) ----------------
__device__ float g_Q [BB*NN*DHH];
__device__ float g_K [BB*NN*DHH];
__device__ float g_V [BB*NN*DHH];
__device__ float g_Ni[BB*NN*DHH];
__device__ float g_Nj[BB*NN*DHH];
__device__ float g_Att[BB*NN*NN];          // 2 MB, L2-resident

__device__ __forceinline__ uint32_t f2tf32(float x) {
    uint32_t r;
    asm("cvt.rna.tf32.f32 %0, %1;" : "=r"(r) : "f"(x));
    return r;
}
__device__ __forceinline__ void mma_tf32(float* d, const uint32_t* a,
                                         const uint32_t* b) {
    asm volatile(
        "mma.sync.aligned.m16n8k8.row.col.f32.tf32.tf32.f32 "
        "{%0,%1,%2,%3}, {%4,%5,%6,%7}, {%8,%9}, {%0,%1,%2,%3};"
        : "+f"(d[0]), "+f"(d[1]), "+f"(d[2]), "+f"(d[3])
        : "r"(a[0]), "r"(a[1]), "r"(a[2]), "r"(a[3]), "r"(b[0]), "r"(b[1]));
}

// ================= K1: node projections Q,K,V,Ni,Nj =================
__global__ void proj_kernel(const float* __restrict__ x,
                            const float* __restrict__ Wq,  const float* __restrict__ bq,
                            const float* __restrict__ Wk,  const float* __restrict__ bk,
                            const float* __restrict__ Wv,  const float* __restrict__ bv,
                            const float* __restrict__ Wni, const float* __restrict__ bni,
                            const float* __restrict__ Wnj, const float* __restrict__ bnj) {
    __shared__ float xs[DD];
    const int blk = blockIdx.x;          // b*N + n
    const int t = threadIdx.x;
    xs[t]       = x[blk*DD + t];
    xs[t + 128] = x[blk*DD + t + 128];
    __syncthreads();
    if (t < 80) {
        const int p = t >> 4, h = t & 15;
        const float* W; const float* bias; float* o;
        if      (p == 0) { W = Wq;  bias = bq;  o = g_Q;  }
        else if (p == 1) { W = Wk;  bias = bk;  o = g_K;  }
        else if (p == 2) { W = Wv;  bias = bv;  o = g_V;  }
        else if (p == 3) { W = Wni; bias = bni; o = g_Ni; }
        else             { W = Wnj; bias = bnj; o = g_Nj; }
        float acc = bias[h];
        #pragma unroll 8
        for (int d = 0; d < DD; d++) acc = fmaf(xs[d], W[d*DHH + h], acc);
        o[blk*DHH + h] = acc;
    }
}

// ================= K2: edge projection via mma.sync tf32 (family-common ISA) =================
// One block per (b,i). 256 threads / 8 warps. Warp w owns rows [64w, 64w+64):
// 4 m16 tiles x 2 n8 tiles of m16n8k8 tf32 mma, K chunked by 32 (4 k-steps).
// Staging identical to the proven R7 pipeline: LDG->reg prefetch (chunk c+1 in
// flight during chunk c compute) -> cvt.rna.tf32 -> swizzle-free padded STS.
// A fragments via conflict-free LDS.32 (bank = (4g+c)&31, all distinct).
// Epilogue: acc tiles -> smem (stride 20) -> per-row e_new + Att (R7 code).
#define ECHUNK 32
#define ASTR   36
#define ESTR   20
#define E_SMEM_BYTES ((DD*DHH + NN*ASTR + 32) * 4)

__global__ __launch_bounds__(256) void edge_kernel(const float* __restrict__ e,
                                                   const float* __restrict__ We,
                                                   const float* __restrict__ be,
                                                   float* __restrict__ outE) {
    extern __shared__ float sm[];
    float*    We_s = sm;                   // 4096 floats (tf32 bits), 16 KB
    uint32_t* WeB  = (uint32_t*)We_s;
    float*    As   = sm + DD*DHH;          // 512*36 floats (72 KB); reused as Es
    uint32_t* AsB  = (uint32_t*)As;
    float*    Qs   = As + NN*ASTR;         // 16
    float*    NiBe = Qs + 16;              // 16

    const int tid  = threadIdx.x;
    const int wid  = tid >> 5;
    const int lane = tid & 31;
    const int g    = lane >> 2;            // group row
    const int cq   = lane & 3;             // col-in-group
    const int blk  = blockIdx.x;           // b*N + i
    const int b    = blk >> 9;

    // stage We ([d][h] row-major) as tf32 bits
    for (int idx = tid; idx < DD*DHH; idx += 256)
        WeB[idx] = f2tf32(We[idx]);
    if (tid < DHH) {
        Qs[tid]   = g_Q [blk*DHH + tid];
        NiBe[tid] = g_Ni[blk*DHH + tid] + be[tid];
    }

    const float* erow = e + (size_t)blk * (NN*DD);
    const int srow = tid >> 3;             // 8 lanes cover one 128B row-line
    const int skl  = (tid & 7) << 2;

    float4 pref[16];
    // ---- prologue: fetch chunk 0, convert, stage ----
    #pragma unroll
    for (int it = 0; it < 16; it++)
        pref[it] = *(const float4*)(erow + (size_t)(srow + it*32)*DD + skl);
    #pragma unroll
    for (int it = 0; it < 16; it++) {
        uint4 v;
        v.x = f2tf32(pref[it].x); v.y = f2tf32(pref[it].y);
        v.z = f2tf32(pref[it].z); v.w = f2tf32(pref[it].w);
        *(uint4*)&AsB[(srow + it*32)*ASTR + skl] = v;
    }
    __syncthreads();

    float acc[4][2][4];                    // [m-tile][n-tile][frag]
    #pragma unroll
    for (int mt = 0; mt < 4; mt++)
        #pragma unroll
        for (int nt = 0; nt < 2; nt++)
            #pragma unroll
            for (int q = 0; q < 4; q++) acc[mt][nt][q] = 0.f;

    #pragma unroll 1
    for (int c = 0; c < DD/ECHUNK; c++) {
        // prefetch chunk c+1 (in flight during mma compute)
        if (c < DD/ECHUNK - 1) {
            const int dbn = (c + 1) * ECHUNK;
            #pragma unroll
            for (int it = 0; it < 16; it++)
                pref[it] = *(const float4*)(erow + (size_t)(srow + it*32)*DD + dbn + skl);
        }
        // ---- compute chunk c with mma.sync tf32 ----
        const int dbase = c * ECHUNK;
        uint32_t bf[4][2][2];              // [k-step][n-tile][2]
        #pragma unroll
        for (int kt = 0; kt < 4; kt++)
            #pragma unroll
            for (int nt = 0; nt < 2; nt++) {
                bf[kt][nt][0] = WeB[(dbase + kt*8 + cq    )*DHH + nt*8 + g];
                bf[kt][nt][1] = WeB[(dbase + kt*8 + cq + 4)*DHH + nt*8 + g];
            }
        const int rw = wid*64;
        #pragma unroll
        for (int mt = 0; mt < 4; mt++) {
            const int r0 = (rw + mt*16 + g)*ASTR;
            const int r1 = r0 + 8*ASTR;
            #pragma unroll
            for (int kt = 0; kt < 4; kt++) {
                uint32_t af[4];
                af[0] = AsB[r0 + kt*8 + cq];
                af[1] = AsB[r1 + kt*8 + cq];
                af[2] = AsB[r0 + kt*8 + cq + 4];
                af[3] = AsB[r1 + kt*8 + cq + 4];
                mma_tf32(acc[mt][0], af, bf[kt][0]);
                mma_tf32(acc[mt][1], af, bf[kt][1]);
            }
        }
        __syncthreads();                   // readers done with As
        if (c < DD/ECHUNK - 1) {
            #pragma unroll
            for (int it = 0; it < 16; it++) {
                uint4 v;
                v.x = f2tf32(pref[it].x); v.y = f2tf32(pref[it].y);
                v.z = f2tf32(pref[it].z); v.w = f2tf32(pref[it].w);
                *(uint4*)&AsB[(srow + it*32)*ASTR + skl] = v;
            }
        }
        __syncthreads();                   // As holds chunk c+1
    }

    // ---- epilogue stage 1: acc tiles -> smem Es (row-major, stride 20) ----
    float* Es = As;                        // As free now
    #pragma unroll
    for (int mt = 0; mt < 4; mt++) {
        const int r0 = wid*64 + mt*16 + g;
        #pragma unroll
        for (int nt = 0; nt < 2; nt++) {
            const int c0 = nt*8 + 2*cq;
            *(float2*)&Es[ r0      *ESTR + c0] = make_float2(acc[mt][nt][0], acc[mt][nt][1]);
            *(float2*)&Es[(r0 + 8)*ESTR + c0] = make_float2(acc[mt][nt][2], acc[mt][nt][3]);
        }
    }
    __syncthreads();

    // ---- epilogue stage 2: e_new = E + be + Ni + Nj ; Att = dot(e_new, Q*K)/4 ----
    float attv[2];
    #pragma unroll
    for (int r = 0; r < 2; r++) {
        const int j = tid + r*256;
        float en[16];
        #pragma unroll
        for (int q4 = 0; q4 < 4; q4++)
            *(float4*)&en[q4*4] = *(const float4*)&Es[j*ESTR + q4*4];
        const float4* njp = (const float4*)&g_Nj[((size_t)b*NN + j)*DHH];
        const float4* kp  = (const float4*)&g_K [((size_t)b*NN + j)*DHH];
        float4* eo = (float4*)(outE + ((size_t)blk*NN + j)*DHH);
        float att = 0.f;
        #pragma unroll
        for (int q4 = 0; q4 < 4; q4++) {
            const float4 nj = njp[q4], kk = kp[q4];
            float4 ev;
            ev.x = en[4*q4+0] + NiBe[4*q4+0] + nj.x;
            ev.y = en[4*q4+1] + NiBe[4*q4+1] + nj.y;
            ev.z = en[4*q4+2] + NiBe[4*q4+2] + nj.z;
            ev.w = en[4*q4+3] + NiBe[4*q4+3] + nj.w;
            att = fmaf(ev.x, Qs[4*q4+0]*kk.x, att);
            att = fmaf(ev.y, Qs[4*q4+1]*kk.y, att);
            att = fmaf(ev.z, Qs[4*q4+2]*kk.z, att);
            att = fmaf(ev.w, Qs[4*q4+3]*kk.w, att);
            eo[q4] = ev;
        }
        attv[r] = att * 0.25f;             // / sqrt(DH=16)
    }
    g_Att[(size_t)blk*NN + tid]       = attv[0];
    g_Att[(size_t)blk*NN + tid + 256] = attv[1];
}

// ================= K3: softmax over axis i (per (b,j) column), in place =================
__global__ void softmax_kernel() {
    __shared__ float red[8];
    __shared__ float sval;
    const int blk = blockIdx.x;              // b*N + j
    const int b = blk >> 9, j = blk & 511;
    const int t = threadIdx.x;               // 256
    float* base = g_Att + (size_t)b*NN*NN + j;
    float v0 = base[(size_t)t*NN];
    float v1 = base[(size_t)(t + 256)*NN];

    float m = fmaxf(v0, v1);
    #pragma unroll
    for (int o = 16; o > 0; o >>= 1) m = fmaxf(m, __shfl_xor_sync(0xffffffffu, m, o));
    if ((t & 31) == 0) red[t >> 5] = m;
    __syncthreads();
    if (t == 0) {
        float mm = red[0];
        #pragma unroll
        for (int k = 1; k < 8; k++) mm = fmaxf(mm, red[k]);
        sval = mm;
    }
    __syncthreads();
    const float mx = sval;
    float e0 = __expf(v0 - mx), e1 = __expf(v1 - mx);
    float s = e0 + e1;
    #pragma unroll
    for (int o = 16; o > 0; o >>= 1) s += __shfl_xor_sync(0xffffffffu, s, o);
    if ((t & 31) == 0) red[t >> 5] = s;
    __syncthreads();
    if (t == 0) {
        float ss = 0.f;
        #pragma unroll
        for (int k = 0; k < 8; k++) ss += red[k];
        sval = ss;
    }
    __syncthreads();
    const float inv = 1.0f / sval;
    base[(size_t)t*NN]         = e0 * inv;
    base[(size_t)(t + 256)*NN] = e1 * inv;
}

// ================= K4: out = Att @ V (block per (b,i), tree reduction) =================
__global__ void out_kernel(float* __restrict__ out) {
    __shared__ float red[128][20];
    const int blk = blockIdx.x;              // b*N + i
    const int b = blk >> 9;
    const int t = threadIdx.x;               // 128
    const float* arow = g_Att + (size_t)blk*NN;
    float acc[16];
    #pragma unroll
    for (int h = 0; h < 16; h++) acc[h] = 0.f;
    #pragma unroll
    for (int r = 0; r < 4; r++) {
        const int j = t + r*128;
        const float a = arow[j];
        const float4* v = (const float4*)&g_V[((size_t)b*NN + j)*DHH];
        float4 v0 = v[0], v1 = v[1], v2 = v[2], v3 = v[3];
        acc[0]  = fmaf(a, v0.x, acc[0]);  acc[1]  = fmaf(a, v0.y, acc[1]);
        acc[2]  = fmaf(a, v0.z, acc[2]);  acc[3]  = fmaf(a, v0.w, acc[3]);
        acc[4]  = fmaf(a, v1.x, acc[4]);  acc[5]  = fmaf(a, v1.y, acc[5]);
        acc[6]  = fmaf(a, v1.z, acc[6]);  acc[7]  = fmaf(a, v1.w, acc[7]);
        acc[8]  = fmaf(a, v2.x, acc[8]);  acc[9]  = fmaf(a, v2.y, acc[9]);
        acc[10] = fmaf(a, v2.z, acc[10]); acc[11] = fmaf(a, v2.w, acc[11]);
        acc[12] = fmaf(a, v3.x, acc[12]); acc[13] = fmaf(a, v3.y, acc[13]);
        acc[14] = fmaf(a, v3.z, acc[14]); acc[15] = fmaf(a, v3.w, acc[15]);
    }
    #pragma unroll
    for (int q4 = 0; q4 < 4; q4++)
        *(float4*)&red[t][q4*4] = *(float4*)&acc[q4*4];
    __syncthreads();
    #pragma unroll
    for (int s = 64; s > 0; s >>= 1) {
        if (t < s) {
            #pragma unroll
            for (int q4 = 0; q4 < 4; q4++) {
                float4 x = *(float4*)&red[t][q4*4];
                float4 y = *(float4*)&red[t + s][q4*4];
                x.x += y.x; x.y += y.y; x.z += y.z; x.w += y.w;
                *(float4*)&red[t][q4*4] = x;
            }
        }
        __syncthreads();
    }
    if (t < DHH) out[blk*DHH + t] = red[0][t];
}

// ================= launch =================
extern "C" void kernel_launch(void* const* d_in, const int* in_sizes, int n_in,
                              void* d_out, int out_size) {
    const float* x   = (const float*)d_in[0];
    const float* e   = (const float*)d_in[1];
    const float* Wq  = (const float*)d_in[2];
    const float* bq  = (const float*)d_in[3];
    const float* Wk  = (const float*)d_in[4];
    const float* bk  = (const float*)d_in[5];
    const float* We  = (const float*)d_in[6];
    const float* be  = (const float*)d_in[7];
    const float* Wv  = (const float*)d_in[8];
    const float* bv  = (const float*)d_in[9];
    const float* Wni = (const float*)d_in[10];
    const float* bni = (const float*)d_in[11];
    const float* Wnj = (const float*)d_in[12];
    const float* bnj = (const float*)d_in[13];

    float* out  = (float*)d_out;              // [B,N,DH] first
    float* outE = out + BB*NN*DHH;            // then e_new [B,N,N,DH]

    cudaFuncSetAttribute(edge_kernel, cudaFuncAttributeMaxDynamicSharedMemorySize,
                         E_SMEM_BYTES);

    proj_kernel   <<<BB*NN, 128>>>(x, Wq, bq, Wk, bk, Wv, bv, Wni, bni, Wnj, bnj);
    edge_kernel   <<<BB*NN, 256, E_SMEM_BYTES>>>(e, We, be, outE);
    softmax_kernel<<<BB*NN, 256>>>();
    out_kernel    <<<BB*NN, 128>>>(out);
}

// round 17
// speedup vs baseline: 1.0274x; 1.0274x over previous
#include <cuda_runtime.h>
#include <cstdint>
#include <cstddef>

#define BB  2
#define NN  512
#define DD  256
#define DHH 16

// ---------------- scratch (no allocations allowed) ----------------
__device__ float g_Q [BB*NN*DHH];
__device__ float g_K [BB*NN*DHH];
__device__ float g_V [BB*NN*DHH];
__device__ float g_Ni[BB*NN*DHH];
__device__ float g_Nj[BB*NN*DHH];
__device__ float g_Att[BB*NN*NN];          // 2 MB, L2-resident

__device__ __forceinline__ uint32_t f2tf32(float x) {
    uint32_t r;
    asm("cvt.rna.tf32.f32 %0, %1;" : "=r"(r) : "f"(x));
    return r;
}
__device__ __forceinline__ void mma_tf32(float* d, const uint32_t* a,
                                         const uint32_t* b) {
    asm volatile(
        "mma.sync.aligned.m16n8k8.row.col.f32.tf32.tf32.f32 "
        "{%0,%1,%2,%3}, {%4,%5,%6,%7}, {%8,%9}, {%0,%1,%2,%3};"
        : "+f"(d[0]), "+f"(d[1]), "+f"(d[2]), "+f"(d[3])
        : "r"(a[0]), "r"(a[1]), "r"(a[2]), "r"(a[3]), "r"(b[0]), "r"(b[1]));
}

// ================= K1: node projections Q,K,V,Ni,Nj =================
__global__ void proj_kernel(const float* __restrict__ x,
                            const float* __restrict__ Wq,  const float* __restrict__ bq,
                            const float* __restrict__ Wk,  const float* __restrict__ bk,
                            const float* __restrict__ Wv,  const float* __restrict__ bv,
                            const float* __restrict__ Wni, const float* __restrict__ bni,
                            const float* __restrict__ Wnj, const float* __restrict__ bnj) {
    __shared__ float xs[DD];
    const int blk = blockIdx.x;          // b*N + n
    const int t = threadIdx.x;
    xs[t]       = x[blk*DD + t];
    xs[t + 128] = x[blk*DD + t + 128];
    __syncthreads();
    if (t < 80) {
        const int p = t >> 4, h = t & 15;
        const float* W; const float* bias; float* o;
        if      (p == 0) { W = Wq;  bias = bq;  o = g_Q;  }
        else if (p == 1) { W = Wk;  bias = bk;  o = g_K;  }
        else if (p == 2) { W = Wv;  bias = bv;  o = g_V;  }
        else if (p == 3) { W = Wni; bias = bni; o = g_Ni; }
        else             { W = Wnj; bias = bnj; o = g_Nj; }
        float acc = bias[h];
        #pragma unroll 8
        for (int d = 0; d < DD; d++) acc = fmaf(xs[d], W[d*DHH + h], acc);
        o[blk*DHH + h] = acc;
    }
}

// ================= K2: edge projection via mma.sync tf32, 2 CTAs per (b,i) =================
// [R16 resubmit of the untested R15 occupancy-4 design; R15 bench was an
// infra flake (failed identically on an empty stub in R0).]
// Grid 2048: CTA handles 256 rows (half of one (b,i)). 128 threads / 4 warps;
// warp w owns 64 rows = 4 m16 tiles x 2 n8 tiles of m16n8k8 tf32. K chunked by
// 32. 53KB smem + <=128 regs -> 4 CTAs/SM: cross-CTA overlap hides the
// per-CTA [LDG-wait -> STS -> bar -> compute -> bar] serialization that bound
// the occupancy-1 R7/R12 kernels. LDG batched 8 float4 at a time.
#define ECHUNK 32
#define ASTR   36
#define ROWS   256
#define ESTR   20
#define E_SMEM_BYTES ((DD*DHH + ROWS*ASTR + 32) * 4)

__global__ __launch_bounds__(128, 4) void edge_kernel(const float* __restrict__ e,
                                                      const float* __restrict__ We,
                                                      const float* __restrict__ be,
                                                      float* __restrict__ outE) {
    extern __shared__ float sm[];
    float*    We_s = sm;                   // 4096 floats (tf32 bits), 16 KB
    uint32_t* WeB  = (uint32_t*)We_s;
    float*    As   = sm + DD*DHH;          // 256*36 floats (36 KB); reused as Es
    uint32_t* AsB  = (uint32_t*)As;
    float*    Qs   = As + ROWS*ASTR;       // 16
    float*    NiBe = Qs + 16;              // 16

    const int tid  = threadIdx.x;
    const int wid  = tid >> 5;
    const int lane = tid & 31;
    const int g    = lane >> 2;            // group row
    const int cq   = lane & 3;             // col-in-group
    const int blk  = blockIdx.x;           // 2*(b*N+i) + half
    const int pair = blk >> 1;             // b*N + i
    const int half = blk & 1;
    const int b    = pair >> 9;

    // stage We ([d][h] row-major) as tf32 bits
    for (int idx = tid; idx < DD*DHH; idx += 128)
        WeB[idx] = f2tf32(We[idx]);
    if (tid < DHH) {
        Qs[tid]   = g_Q [pair*DHH + tid];
        NiBe[tid] = g_Ni[pair*DHH + tid] + be[tid];
    }

    const float* erow = e + (size_t)pair * (NN*DD) + (size_t)half * (ROWS*DD);
    const int srow = tid >> 3;             // 0..15; 8 lanes cover one 128B row-line
    const int skl  = (tid & 7) << 2;

    float acc[4][2][4];                    // [m-tile][n-tile][frag]
    #pragma unroll
    for (int mt = 0; mt < 4; mt++)
        #pragma unroll
        for (int nt = 0; nt < 2; nt++)
            #pragma unroll
            for (int q = 0; q < 4; q++) acc[mt][nt][q] = 0.f;
    __syncthreads();                       // We_s ready

    #pragma unroll 1
    for (int c = 0; c < DD/ECHUNK; c++) {
        const int dbase = c * ECHUNK;
        // ---- stage chunk c: 256 rows x 32 floats, in two 8-float4 batches ----
        #pragma unroll
        for (int h = 0; h < 2; h++) {
            float4 pf[8];
            #pragma unroll
            for (int it = 0; it < 8; it++) {
                const int row = srow + (h*8 + it)*16;
                pf[it] = *(const float4*)(erow + (size_t)row*DD + dbase + skl);
            }
            #pragma unroll
            for (int it = 0; it < 8; it++) {
                const int row = srow + (h*8 + it)*16;
                uint4 v;
                v.x = f2tf32(pf[it].x); v.y = f2tf32(pf[it].y);
                v.z = f2tf32(pf[it].z); v.w = f2tf32(pf[it].w);
                *(uint4*)&AsB[row*ASTR + skl] = v;
            }
        }
        __syncthreads();
        // ---- compute chunk c ----
        uint32_t bf[4][2][2];              // [k-step][n-tile][2]
        #pragma unroll
        for (int kt = 0; kt < 4; kt++)
            #pragma unroll
            for (int nt = 0; nt < 2; nt++) {
                bf[kt][nt][0] = WeB[(dbase + kt*8 + cq    )*DHH + nt*8 + g];
                bf[kt][nt][1] = WeB[(dbase + kt*8 + cq + 4)*DHH + nt*8 + g];
            }
        const int rw = wid*64;
        #pragma unroll
        for (int mt = 0; mt < 4; mt++) {
            const int r0 = (rw + mt*16 + g)*ASTR;
            const int r1 = r0 + 8*ASTR;
            #pragma unroll
            for (int kt = 0; kt < 4; kt++) {
                uint32_t af[4];
                af[0] = AsB[r0 + kt*8 + cq];
                af[1] = AsB[r1 + kt*8 + cq];
                af[2] = AsB[r0 + kt*8 + cq + 4];
                af[3] = AsB[r1 + kt*8 + cq + 4];
                mma_tf32(acc[mt][0], af, bf[kt][0]);
                mma_tf32(acc[mt][1], af, bf[kt][1]);
            }
        }
        __syncthreads();
    }

    // ---- epilogue stage 1: acc tiles -> smem Es (row-major, stride 20) ----
    float* Es = As;                        // As free now
    #pragma unroll
    for (int mt = 0; mt < 4; mt++) {
        const int r0 = wid*64 + mt*16 + g;
        #pragma unroll
        for (int nt = 0; nt < 2; nt++) {
            const int c0 = nt*8 + 2*cq;
            *(float2*)&Es[ r0      *ESTR + c0] = make_float2(acc[mt][nt][0], acc[mt][nt][1]);
            *(float2*)&Es[(r0 + 8)*ESTR + c0] = make_float2(acc[mt][nt][2], acc[mt][nt][3]);
        }
    }
    __syncthreads();

    // ---- epilogue stage 2: e_new = E + be + Ni + Nj ; Att = dot(e_new, Q*K)/4 ----
    #pragma unroll
    for (int r = 0; r < 2; r++) {
        const int jl = tid + r*128;                 // local row 0..255
        const int j  = half*ROWS + jl;              // global j
        float en[16];
        #pragma unroll
        for (int q4 = 0; q4 < 4; q4++)
            *(float4*)&en[q4*4] = *(const float4*)&Es[jl*ESTR + q4*4];
        const float4* njp = (const float4*)&g_Nj[((size_t)b*NN + j)*DHH];
        const float4* kp  = (const float4*)&g_K [((size_t)b*NN + j)*DHH];
        float4* eo = (float4*)(outE + ((size_t)pair*NN + j)*DHH);
        float att = 0.f;
        #pragma unroll
        for (int q4 = 0; q4 < 4; q4++) {
            const float4 nj = njp[q4], kk = kp[q4];
            float4 ev;
            ev.x = en[4*q4+0] + NiBe[4*q4+0] + nj.x;
            ev.y = en[4*q4+1] + NiBe[4*q4+1] + nj.y;
            ev.z = en[4*q4+2] + NiBe[4*q4+2] + nj.z;
            ev.w = en[4*q4+3] + NiBe[4*q4+3] + nj.w;
            att = fmaf(ev.x, Qs[4*q4+0]*kk.x, att);
            att = fmaf(ev.y, Qs[4*q4+1]*kk.y, att);
            att = fmaf(ev.z, Qs[4*q4+2]*kk.z, att);
            att = fmaf(ev.w, Qs[4*q4+3]*kk.w, att);
            eo[q4] = ev;
        }
        g_Att[(size_t)pair*NN + j] = att * 0.25f;   // / sqrt(DH=16)
    }
}

// ================= K3: softmax over axis i (per (b,j) column), in place =================
__global__ void softmax_kernel() {
    __shared__ float red[8];
    __shared__ float sval;
    const int blk = blockIdx.x;              // b*N + j
    const int b = blk >> 9, j = blk & 511;
    const int t = threadIdx.x;               // 256
    float* base = g_Att + (size_t)b*NN*NN + j;
    float v0 = base[(size_t)t*NN];
    float v1 = base[(size_t)(t + 256)*NN];

    float m = fmaxf(v0, v1);
    #pragma unroll
    for (int o = 16; o > 0; o >>= 1) m = fmaxf(m, __shfl_xor_sync(0xffffffffu, m, o));
    if ((t & 31) == 0) red[t >> 5] = m;
    __syncthreads();
    if (t == 0) {
        float mm = red[0];
        #pragma unroll
        for (int k = 1; k < 8; k++) mm = fmaxf(mm, red[k]);
        sval = mm;
    }
    __syncthreads();
    const float mx = sval;
    float e0 = __expf(v0 - mx), e1 = __expf(v1 - mx);
    float s = e0 + e1;
    #pragma unroll
    for (int o = 16; o > 0; o >>= 1) s += __shfl_xor_sync(0xffffffffu, s, o);
    if ((t & 31) == 0) red[t >> 5] = s;
    __syncthreads();
    if (t == 0) {
        float ss = 0.f;
        #pragma unroll
        for (int k = 0; k < 8; k++) ss += red[k];
        sval = ss;
    }
    __syncthreads();
    const float inv = 1.0f / sval;
    base[(size_t)t*NN]         = e0 * inv;
    base[(size_t)(t + 256)*NN] = e1 * inv;
}

// ================= K4: out = Att @ V (block per (b,i), tree reduction) =================
__global__ void out_kernel(float* __restrict__ out) {
    __shared__ float red[128][20];
    const int blk = blockIdx.x;              // b*N + i
    const int b = blk >> 9;
    const int t = threadIdx.x;               // 128
    const float* arow = g_Att + (size_t)blk*NN;
    float acc[16];
    #pragma unroll
    for (int h = 0; h < 16; h++) acc[h] = 0.f;
    #pragma unroll
    for (int r = 0; r < 4; r++) {
        const int j = t + r*128;
        const float a = arow[j];
        const float4* v = (const float4*)&g_V[((size_t)b*NN + j)*DHH];
        float4 v0 = v[0], v1 = v[1], v2 = v[2], v3 = v[3];
        acc[0]  = fmaf(a, v0.x, acc[0]);  acc[1]  = fmaf(a, v0.y, acc[1]);
        acc[2]  = fmaf(a, v0.z, acc[2]);  acc[3]  = fmaf(a, v0.w, acc[3]);
        acc[4]  = fmaf(a, v1.x, acc[4]);  acc[5]  = fmaf(a, v1.y, acc[5]);
        acc[6]  = fmaf(a, v1.z, acc[6]);  acc[7]  = fmaf(a, v1.w, acc[7]);
        acc[8]  = fmaf(a, v2.x, acc[8]);  acc[9]  = fmaf(a, v2.y, acc[9]);
        acc[10] = fmaf(a, v2.z, acc[10]); acc[11] = fmaf(a, v2.w, acc[11]);
        acc[12] = fmaf(a, v3.x, acc[12]); acc[13] = fmaf(a, v3.y, acc[13]);
        acc[14] = fmaf(a, v3.z, acc[14]); acc[15] = fmaf(a, v3.w, acc[15]);
    }
    #pragma unroll
    for (int q4 = 0; q4 < 4; q4++)
        *(float4*)&red[t][q4*4] = *(float4*)&acc[q4*4];
    __syncthreads();
    #pragma unroll
    for (int s = 64; s > 0; s >>= 1) {
        if (t < s) {
            #pragma unroll
            for (int q4 = 0; q4 < 4; q4++) {
                float4 x = *(float4*)&red[t][q4*4];
                float4 y = *(float4*)&red[t + s][q4*4];
                x.x += y.x; x.y += y.y; x.z += y.z; x.w += y.w;
                *(float4*)&red[t][q4*4] = x;
            }
        }
        __syncthreads();
    }
    if (t < DHH) out[blk*DHH + t] = red[0][t];
}

// ================= launch =================
extern "C" void kernel_launch(void* const* d_in, const int* in_sizes, int n_in,
                              void* d_out, int out_size) {
    const float* x   = (const float*)d_in[0];
    const float* e   = (const float*)d_in[1];
    const float* Wq  = (const float*)d_in[2];
    const float* bq  = (const float*)d_in[3];
    const float* Wk  = (const float*)d_in[4];
    const float* bk  = (const float*)d_in[5];
    const float* We  = (const float*)d_in[6];
    const float* be  = (const float*)d_in[7];
    const float* Wv  = (const float*)d_in[8];
    const float* bv  = (const float*)d_in[9];
    const float* Wni = (const float*)d_in[10];
    const float* bni = (const float*)d_in[11];
    const float* Wnj = (const float*)d_in[12];
    const float* bnj = (const float*)d_in[13];

    float* out  = (float*)d_out;              // [B,N,DH] first
    float* outE = out + BB*NN*DHH;            // then e_new [B,N,N,DH]

    cudaFuncSetAttribute(edge_kernel, cudaFuncAttributeMaxDynamicSharedMemorySize,
                         E_SMEM_BYTES);

    proj_kernel   <<<BB*NN, 128>>>(x, Wq, bq, Wk, bk, Wv, bv, Wni, bni, Wnj, bnj);
    edge_kernel   <<<BB*NN*2, 128, E_SMEM_BYTES>>>(e, We, be, outE);
    softmax_kernel<<<BB*NN, 256>>>();
    out_kernel    <<<BB*NN, 128>>>(out);
}